// round 1
// baseline (speedup 1.0000x reference)
#include <cuda_runtime.h>
#include <math.h>

#define NENT 50000
#define NPAD 50048
#define NEDGE 400000
#define BQ 32
#define HID 128
#define G4 512

// ---------------- scratch (device globals; no allocation) ----------------
__device__ __align__(16) float g_Wperm[2*G4*HID];      // entity Whh, gate-interleaved cols
__device__ __align__(16) float g_Ppre[2*25*G4];        // entity input-proj LUT (+biases), permuted
__device__ __align__(16) float g_h0[NPAD*HID];
__device__ __align__(16) float g_h1[NPAD*HID];
__device__ __align__(16) float g_c[NPAD*HID];
__device__ __align__(16) float g_hF[NENT*HID];
__device__ __align__(16) float g_hB[NENT*HID];
__device__ float g_eattn[NENT*24];
__device__ float g_w[NEDGE];
__device__ __align__(16) float g_Wqperm[6*G4*HID];     // query Whh (r,dir) permuted
__device__ __align__(16) float g_Pq[6*BQ*G4];          // query input-proj (+biases), permuted
__device__ __align__(16) float g_qh[18*BQ*HID];        // [pair(6)][step(3)][b][u]
__device__ float g_qc[6*BQ*HID];
__device__ float g_qattn[9*BQ*25];                     // [r*3+t][b][op]
__device__ float g_mem[NENT*BQ];
__device__ float g_added[NENT*BQ];
__device__ float g_sums[BQ];

__device__ __forceinline__ float sigm(float x){ return 1.f/(1.f+expf(-x)); }

// ---------------- preprocessing: permuted weights + input-projection LUTs ----------------
// permutation: col p <- gate j = (p%4)*128 + p/4, so a 4-aligned micro-tile = (i,f,g,o) of one unit
#define S1 131072              // entity Wperm          2*512*128
#define S2 25600               // entity Ppre           2*25*512 (128-dot each)
#define S3 12288               // zero pad rows of h0/h1
#define S4 393216              // query Wqperm          6*512*128
#define S5 98304               // query Pq              6*32*512 (128-dot each)
#define PREP_TOT (S1+S2+S3+S4+S5)

__global__ void prep_kernel(const float* __restrict__ eWih, const float* __restrict__ eWhh,
                            const float* __restrict__ ebih, const float* __restrict__ ebhh,
                            const float* __restrict__ eemb,
                            const float* __restrict__ qWih, const float* __restrict__ qWhh,
                            const float* __restrict__ qbih, const float* __restrict__ qbhh,
                            const float* __restrict__ qemb, const int* __restrict__ queries){
    int idx = blockIdx.x*blockDim.x + threadIdx.x;
    if (idx < S1){
        int dir = idx >> 16; int rem = idx & 65535; int p = rem >> 7; int k = rem & 127;
        int j = ((p&3)<<7) + (p>>2);
        g_Wperm[idx] = eWhh[(dir<<16) + (j<<7) + k];
        return;
    }
    idx -= S1;
    if (idx < S2){
        int dir = idx / 12800; int rem = idx % 12800; int v = rem >> 9; int p = rem & 511;
        int j = ((p&3)<<7) + (p>>2);
        float acc = ebih[(dir<<9)+j] + ebhh[(dir<<9)+j];
        const float* wr = eWih + (dir<<16) + (j<<7);
        const float* er = eemb + (v<<7);
        for (int k=0;k<128;k++) acc += er[k]*wr[k];
        g_Ppre[(dir*12800) + (v<<9) + p] = acc;
        return;
    }
    idx -= S2;
    if (idx < S3){
        int which = idx / 6144; int off = idx % 6144;
        (which? g_h1 : g_h0)[NENT*HID + off] = 0.f;
        return;
    }
    idx -= S3;
    if (idx < S4){
        int pr = idx >> 16; int rem = idx & 65535; int p = rem >> 7; int k = rem & 127;
        int j = ((p&3)<<7) + (p>>2);
        g_Wqperm[idx] = qWhh[(pr<<16) + (j<<7) + k];
        return;
    }
    idx -= S4;
    if (idx < S5){
        int pr = idx >> 14; int rem = idx & 16383; int b = rem >> 9; int p = rem & 511;
        int j = ((p&3)<<7) + (p>>2);
        float acc = qbih[(pr<<9)+j] + qbhh[(pr<<9)+j];
        const float* wr = qWih + (pr<<16) + (j<<7);
        const float* xr = qemb + (queries[b]<<7);
        for (int k=0;k<128;k++) acc += xr[k]*wr[k];
        g_Pq[(pr<<14) + (b<<9) + p] = acc;
    }
}

// ---------------- entity LSTM ----------------
// step 0: h=c=0, gate preact = Ppre LUT only
__global__ void ent_step0(int dir, int tIdx, const int* __restrict__ degs){
    int idx = blockIdx.x*blockDim.x + threadIdx.x;
    if (idx >= NENT*HID) return;
    int m = idx>>7, u = idx&127;
    int d = degs[(m<<3)+tIdx];
    float4 P = *(const float4*)(g_Ppre + (dir*12800) + (d<<9) + (u<<2));
    float cn = sigm(P.x)*tanhf(P.z);          // sig(i)*tanh(g); sig(f)*0 dropped
    g_c[idx]  = cn;
    g_h0[idx] = sigm(P.w)*tanhf(cn);
}

// steps 1..7: fused SGEMM (h @ Whh_perm^T) + LSTM cell epilogue.
// outSel: 0=g_h0 1=g_h1 2=g_hF 3=g_hB
__global__ __launch_bounds__(256) void ent_step(int inSel, int outSel, int dir, int tIdx,
                                                const int* __restrict__ degs){
    const float* h_in = inSel ? g_h1 : g_h0;
    float* h_out = (outSel==0)? g_h0 : (outSel==1)? g_h1 : (outSel==2)? g_hF : g_hB;
    __shared__ float As[16][68];
    __shared__ float Bs[16][68];
    int mBase = blockIdx.y<<6;
    int cb    = blockIdx.x<<6;
    int tid = threadIdx.x;
    int ty = tid>>4, tx = tid&15;
    int lr = tid>>2;
    int kq = (tid&3)<<2;
    const float* Wp = g_Wperm + (dir<<16);
    float acc[4][4] = {};
    for (int kb=0; kb<128; kb+=16){
        float4 a4 = *(const float4*)(h_in + ((mBase+lr)<<7) + kb + kq);
        float4 b4 = *(const float4*)(Wp   + ((cb+lr)<<7)   + kb + kq);
        As[kq+0][lr]=a4.x; As[kq+1][lr]=a4.y; As[kq+2][lr]=a4.z; As[kq+3][lr]=a4.w;
        Bs[kq+0][lr]=b4.x; Bs[kq+1][lr]=b4.y; Bs[kq+2][lr]=b4.z; Bs[kq+3][lr]=b4.w;
        __syncthreads();
        #pragma unroll
        for (int k=0;k<16;k++){
            float a0=As[k][(ty<<2)+0], a1=As[k][(ty<<2)+1];
            float a2=As[k][(ty<<2)+2], a3=As[k][(ty<<2)+3];
            float4 b = *(const float4*)&Bs[k][tx<<2];
            acc[0][0]+=a0*b.x; acc[0][1]+=a0*b.y; acc[0][2]+=a0*b.z; acc[0][3]+=a0*b.w;
            acc[1][0]+=a1*b.x; acc[1][1]+=a1*b.y; acc[1][2]+=a1*b.z; acc[1][3]+=a1*b.w;
            acc[2][0]+=a2*b.x; acc[2][1]+=a2*b.y; acc[2][2]+=a2*b.z; acc[2][3]+=a2*b.w;
            acc[3][0]+=a3*b.x; acc[3][1]+=a3*b.y; acc[3][2]+=a3*b.z; acc[3][3]+=a3*b.w;
        }
        __syncthreads();
    }
    int u = (cb>>2) + tx;
    const float* Pb = g_Ppre + (dir*12800) + cb + (tx<<2);
    #pragma unroll
    for (int i=0;i<4;i++){
        int m = mBase + (ty<<2) + i;
        if (m < NENT){
            int d = degs[(m<<3)+tIdx];
            float4 P = *(const float4*)(Pb + (d<<9));
            float ig = sigm (acc[i][0]+P.x);
            float fg = sigm (acc[i][1]+P.y);
            float gg = tanhf(acc[i][2]+P.z);
            float og = sigm (acc[i][3]+P.w);
            int ci = (m<<7)+u;
            float cn = fg*g_c[ci] + ig*gg;
            g_c[ci]  = cn;
            h_out[ci] = og*tanhf(cn);
        }
    }
}

// ---------------- entity attention: softmax(concat(hF,hB) @ W^T + b) ----------------
__global__ void ent_attn_kernel(const float* __restrict__ W, const float* __restrict__ bias){
    __shared__ float Ws[8192];     // [k(256)][op padded to 32]
    int tid = threadIdx.x;
    for (int i=tid;i<8192;i+=256) Ws[i]=0.f;
    __syncthreads();
    for (int i=tid;i<24*256;i+=256){ int o=i>>8, k=i&255; Ws[(k<<5)+o]=W[i]; }
    __syncthreads();
    int lane = tid&31;
    int wid = (blockIdx.x<<3) + (tid>>5);
    int nw  = gridDim.x<<3;
    float bv = (lane<24)? bias[lane] : -1e30f;
    for (int n=wid; n<NENT; n+=nw){
        float acc = bv;
        const float* hf = g_hF + (n<<7);
        const float* hb = g_hB + (n<<7);
        for (int k=0;k<128;k++) acc += hf[k]*Ws[(k<<5)+lane];
        for (int k=0;k<128;k++) acc += hb[k]*Ws[((k+128)<<5)+lane];
        float mx = acc;
        for (int o=16;o;o>>=1) mx = fmaxf(mx, __shfl_xor_sync(0xffffffffu, mx, o));
        float e = (lane<24)? expf(acc-mx) : 0.f;
        float s = e;
        for (int o=16;o;o>>=1) s += __shfl_xor_sync(0xffffffffu, s, o);
        if (lane<24) g_eattn[n*24+lane] = e/s;
    }
}

__global__ void w_gather(const int* __restrict__ th, const int* __restrict__ rl){
    int e = blockIdx.x*blockDim.x + threadIdx.x;
    if (e < NEDGE) g_w[e] = g_eattn[th[e]*24 + rl[e]];
}

// ---------------- query LSTMs (6 (r,dir) pairs, M=32) ----------------
__global__ void q_step0(){
    int idx = blockIdx.x*blockDim.x + threadIdx.x;
    if (idx >= 6*BQ*HID) return;
    int pr = idx/4096; int rem = idx&4095; int b = rem>>7; int u = rem&127;
    float4 P = *(const float4*)(g_Pq + (pr<<14) + (b<<9) + (u<<2));
    float cn = sigm(P.x)*tanhf(P.z);
    g_qc[idx] = cn;
    g_qh[pr*3*4096 + rem] = sigm(P.w)*tanhf(cn);
}

__global__ __launch_bounds__(256) void q_step(int s){
    int pr = blockIdx.y;
    int cb = blockIdx.x<<6;
    const float* h_in = g_qh + (pr*3 + s-1)*4096;
    float* h_out      = g_qh + (pr*3 + s)*4096;
    __shared__ float As[16][36];
    __shared__ float Bs[16][68];
    int tid=threadIdx.x;
    int ty=tid>>4, tx=tid&15;
    const float* Wp = g_Wqperm + (pr<<16);
    float acc[2][4] = {};
    int lrA = tid>>3; int kqA = (tid&7)<<1;
    int lrB = tid>>2; int kqB = (tid&3)<<2;
    for (int kb=0;kb<128;kb+=16){
        float2 a2 = *(const float2*)(h_in + (lrA<<7) + kb + kqA);
        float4 b4 = *(const float4*)(Wp + ((cb+lrB)<<7) + kb + kqB);
        As[kqA+0][lrA]=a2.x; As[kqA+1][lrA]=a2.y;
        Bs[kqB+0][lrB]=b4.x; Bs[kqB+1][lrB]=b4.y; Bs[kqB+2][lrB]=b4.z; Bs[kqB+3][lrB]=b4.w;
        __syncthreads();
        #pragma unroll
        for (int k=0;k<16;k++){
            float a0=As[k][(ty<<1)], a1=As[k][(ty<<1)+1];
            float4 b=*(const float4*)&Bs[k][tx<<2];
            acc[0][0]+=a0*b.x; acc[0][1]+=a0*b.y; acc[0][2]+=a0*b.z; acc[0][3]+=a0*b.w;
            acc[1][0]+=a1*b.x; acc[1][1]+=a1*b.y; acc[1][2]+=a1*b.z; acc[1][3]+=a1*b.w;
        }
        __syncthreads();
    }
    int u = (cb>>2)+tx;
    #pragma unroll
    for (int i=0;i<2;i++){
        int b = (ty<<1)+i;
        float4 P = *(const float4*)(g_Pq + (pr<<14) + (b<<9) + cb + (tx<<2));
        float ig=sigm(acc[i][0]+P.x), fg=sigm(acc[i][1]+P.y);
        float gg=tanhf(acc[i][2]+P.z), og=sigm(acc[i][3]+P.w);
        int ci = pr*4096 + (b<<7) + u;
        float cn = fg*g_qc[ci] + ig*gg;
        g_qc[ci]=cn;
        h_out[(b<<7)+u]=og*tanhf(cn);
    }
}

__global__ void q_attn_kernel(const float* __restrict__ W, const float* __restrict__ bias){
    __shared__ float Ws[8192];
    int tid=threadIdx.x;
    for (int i=tid;i<8192;i+=256) Ws[i]=0.f;
    __syncthreads();
    for (int i=tid;i<25*256;i+=256){ int o=i>>8,k=i&255; Ws[(k<<5)+o]=W[i]; }
    __syncthreads();
    int lane=tid&31;
    int gw=(blockIdx.x<<3)+(tid>>5);
    if (gw>=288) return;
    int b=gw&31, rt=gw>>5; int r=rt/3, t=rt%3;
    const float* hf = g_qh + ((r*2  )*3 + t    )*4096 + (b<<7);
    const float* hb = g_qh + ((r*2+1)*3 + (2-t))*4096 + (b<<7);
    float acc = (lane<25)? bias[lane] : -1e30f;
    for (int k=0;k<128;k++) acc += hf[k]*Ws[(k<<5)+lane];
    for (int k=0;k<128;k++) acc += hb[k]*Ws[((k+128)<<5)+lane];
    float mx=acc;
    for (int o=16;o;o>>=1) mx=fmaxf(mx,__shfl_xor_sync(0xffffffffu,mx,o));
    float e=(lane<25)?expf(acc-mx):0.f;
    float s=e;
    for (int o=16;o;o>>=1) s+=__shfl_xor_sync(0xffffffffu,s,o);
    if (lane<25) g_qattn[rt*800 + b*25 + lane] = e/s;
}

// ---------------- propagation (memory, added laid out (N, B)) ----------------
__global__ void mem_init(const int* __restrict__ heads){
    int idx=blockIdx.x*blockDim.x+threadIdx.x;
    if (idx>=NENT*BQ) return;
    int n=idx>>5, b=idx&31;
    g_mem[idx] = (heads[b]==n)? 1.f : 0.f;
}

__global__ void prop_init(int rt){
    int idx=blockIdx.x*blockDim.x+threadIdx.x;
    if (idx<BQ) g_sums[idx]=0.f;
    if (idx<NENT*BQ)
        g_added[idx] = g_mem[idx]*g_qattn[rt*800 + (idx&31)*25 + 24];
}

__global__ void edge_kernel(int rt, const int* __restrict__ rl,
                            const int* __restrict__ th, const int* __restrict__ tt){
    __shared__ float qs[800];
    const float* qa = g_qattn + rt*800;
    for (int i=threadIdx.x;i<800;i+=blockDim.x) qs[i]=qa[i];
    __syncthreads();
    int lane = threadIdx.x&31;
    int wid = (blockIdx.x*blockDim.x+threadIdx.x)>>5;
    int nw  = (gridDim.x*blockDim.x)>>5;
    for (int e=wid; e<NEDGE; e+=nw){
        int re=rl[e], he=th[e], te=tt[e];
        float we=g_w[e];
        float mh = g_mem[(he<<5)+lane];
        float mt = g_mem[(te<<5)+lane];
        float qf = qs[lane*25+re]*we;
        float qr = qs[lane*25+re+12]*we;
        atomicAdd(&g_added[(te<<5)+lane], qf*mh);
        atomicAdd(&g_added[(he<<5)+lane], qr*mt);
    }
}

__global__ void colsum_kernel(){
    int lane=threadIdx.x&31, w=threadIdx.x>>5;
    float acc=0.f;
    for (int row=(blockIdx.x<<3)+w; row<NENT; row+=gridDim.x<<3)
        acc += g_added[(row<<5)+lane];
    __shared__ float sh[8][32];
    sh[w][lane]=acc;
    __syncthreads();
    if (w==0){
        float s=0.f;
        #pragma unroll
        for (int i=0;i<8;i++) s+=sh[i][lane];
        atomicAdd(&g_sums[lane], s);
    }
}

__global__ void norm_kernel(){
    int idx=blockIdx.x*blockDim.x+threadIdx.x;
    if (idx>=NENT*BQ) return;
    g_mem[idx] = g_added[idx] / fmaxf(1e-20f, g_sums[idx&31]);
}

__global__ void trans_add(float* __restrict__ out, int accum){
    __shared__ float tile[32][33];
    int n0=blockIdx.x<<5;
    int tx=threadIdx.x, ty=threadIdx.y;
    int n=n0+ty;
    tile[ty][tx] = (n<NENT)? g_mem[(n<<5)+tx] : 0.f;
    __syncthreads();
    int nn=n0+tx;
    if (nn<NENT){
        float v=tile[tx][ty];
        if (accum) out[ty*NENT+nn] += v; else out[ty*NENT+nn] = v;
    }
}

// ---------------- host ----------------
extern "C" void kernel_launch(void* const* d_in, const int* in_sizes, int n_in,
                              void* d_out, int out_size){
    const int*   queries=(const int*)d_in[0];
    const int*   heads  =(const int*)d_in[1];
    const int*   rels   =(const int*)d_in[2];
    const int*   t_heads=(const int*)d_in[3];
    const int*   t_tails=(const int*)d_in[4];
    const int*   degs   =(const int*)d_in[5];
    const float* qemb=(const float*)d_in[6];
    const float* eemb=(const float*)d_in[7];
    const float* qWih=(const float*)d_in[8];
    const float* qWhh=(const float*)d_in[9];
    const float* qbih=(const float*)d_in[10];
    const float* qbhh=(const float*)d_in[11];
    const float* eWih=(const float*)d_in[12];
    const float* eWhh=(const float*)d_in[13];
    const float* ebih=(const float*)d_in[14];
    const float* ebhh=(const float*)d_in[15];
    const float* qlW=(const float*)d_in[16];
    const float* qlb=(const float*)d_in[17];
    const float* elW=(const float*)d_in[18];
    const float* elb=(const float*)d_in[19];
    float* out=(float*)d_out;

    prep_kernel<<<(PREP_TOT+255)/256,256>>>(eWih,eWhh,ebih,ebhh,eemb,
                                            qWih,qWhh,qbih,qbhh,qemb,queries);
    // entity BiLSTM: fwd then bwd; ping-pong h0/h1; final h -> hF/hB
    for (int dir=0; dir<2; dir++){
        ent_step0<<<25000,256>>>(dir, dir?7:0, degs);
        for (int s=1; s<8; s++){
            int t = dir? (7-s) : s;
            int outSel = (s==7)? (dir?3:2) : (s&1);
            ent_step<<<dim3(8,782),256>>>((s-1)&1, outSel, dir, t, degs);
        }
    }
    ent_attn_kernel<<<1024,256>>>(elW, elb);
    w_gather<<<(NEDGE+255)/256,256>>>(t_heads, rels);

    // query BiLSTMs (all 6 (r,dir) pairs batched per step)
    q_step0<<<96,256>>>();
    q_step<<<dim3(8,6),256>>>(1);
    q_step<<<dim3(8,6),256>>>(2);
    q_attn_kernel<<<36,256>>>(qlW, qlb);

    // propagation
    for (int r=0; r<3; r++){
        mem_init<<<6250,256>>>(heads);
        for (int t=0; t<3; t++){
            int rt = r*3+t;
            prop_init<<<6250,256>>>(rt);
            edge_kernel<<<1024,256>>>(rt, rels, t_heads, t_tails);
            colsum_kernel<<<512,256>>>();
            norm_kernel<<<6250,256>>>();
        }
        trans_add<<<1563,dim3(32,32)>>>(out, r);
    }
}

// round 3
// speedup vs baseline: 1.3882x; 1.3882x over previous
#include <cuda_runtime.h>
#include <cuda_bf16.h>
#include <math.h>
#include <stdint.h>

#define NENT 50000
#define NPAD 50048
#define MTILES 391
#define NEDGE 400000
#define BQ 32
#define HID 128
#define G4 512

// ---------------- scratch (device globals; no allocation) ----------------
__device__ __align__(16) float g_Ppre[2*25*G4];        // entity input-proj LUT (+biases), (d, 4u+gate)
__device__ __align__(16) float g_c[NPAD*HID];          // cell state, fragment-major layout
__device__ __align__(16) float g_hF[NENT*HID];
__device__ __align__(16) float g_hB[NENT*HID];
__device__ float g_eattn[NENT*24];
__device__ float g_w[NEDGE];
__device__ __align__(16) float g_Wqperm[6*G4*HID];
__device__ __align__(16) float g_Pq[6*BQ*G4];
__device__ __align__(16) float g_qh[18*BQ*HID];
__device__ float g_qc[6*BQ*HID];
__device__ float g_qattn[9*BQ*25];
__device__ float g_mem[NENT*BQ];
__device__ float g_added[NENT*BQ];
__device__ float g_sums[BQ];

// A operands: [buf(2)][plane hi/lo(2)][m NPAD][k 128] bf16
__device__ __align__(16) __nv_bfloat16 g_Amma[2ull*2*NPAD*128];
// B operands: [dir(2)][plane(2)][p 512 (perm gate col)][k 128] bf16
__device__ __align__(16) __nv_bfloat16 g_Bmma[2*2*512*128];

__device__ __forceinline__ float fsigm(float x){
    return __fdividef(1.f, 1.f + __expf(-x));
}
__device__ __forceinline__ float ftanh(float x){
    x = fminf(15.f, fmaxf(-15.f, x));
    float e = __expf(-2.f*x);
    return __fdividef(1.f - e, 1.f + e);
}

__device__ __forceinline__ uint32_t smem_u32(const void* p){
    uint32_t a;
    asm("{ .reg .u64 t; cvta.to.shared.u64 t, %1; cvt.u32.u64 %0, t; }" : "=r"(a) : "l"(p));
    return a;
}

#define LDSM4(r, addr) \
    asm volatile("ldmatrix.sync.aligned.m8n8.x4.shared.b16 {%0,%1,%2,%3}, [%4];" \
        : "=r"((r)[0]),"=r"((r)[1]),"=r"((r)[2]),"=r"((r)[3]) : "r"(addr))

#define MMA16816(d, a, b0, b1) \
    asm volatile("mma.sync.aligned.m16n8k16.row.col.f32.bf16.bf16.f32 " \
        "{%0,%1,%2,%3}, {%4,%5,%6,%7}, {%8,%9}, {%0,%1,%2,%3};" \
        : "+f"((d)[0]),"+f"((d)[1]),"+f"((d)[2]),"+f"((d)[3]) \
        : "r"((a)[0]),"r"((a)[1]),"r"((a)[2]),"r"((a)[3]), "r"(b0),"r"(b1))

// ---------------- preprocessing ----------------
// Ppre permutation: col p -> gate j = (p%4)*128 + p/4  (so float4 at u = (i,f,g,o))
// Bmma permutation: p in [0,512): q=p&15, b=p>>4, u=4b+(q&7)/2, gate = (q<8)?(q&1):2+(q&1)
#define S2 25600               // entity Ppre           2*25*512
#define S4 393216              // query Wqperm          6*512*128
#define S5 98304               // query Pq              6*32*512
#define S6 262144              // g_Bmma                2*2*512*128
#define PREP_TOT (S2+S4+S5+S6)

__global__ void prep_kernel(const float* __restrict__ eWih, const float* __restrict__ eWhh,
                            const float* __restrict__ ebih, const float* __restrict__ ebhh,
                            const float* __restrict__ eemb,
                            const float* __restrict__ qWih, const float* __restrict__ qWhh,
                            const float* __restrict__ qbih, const float* __restrict__ qbhh,
                            const float* __restrict__ qemb, const int* __restrict__ queries){
    int idx = blockIdx.x*blockDim.x + threadIdx.x;
    if (idx < S2){
        int dir = idx / 12800; int rem = idx % 12800; int v = rem >> 9; int p = rem & 511;
        int j = ((p&3)<<7) + (p>>2);
        float acc = ebih[(dir<<9)+j] + ebhh[(dir<<9)+j];
        const float* wr = eWih + (dir<<16) + (j<<7);
        const float* er = eemb + (v<<7);
        for (int k=0;k<128;k++) acc += er[k]*wr[k];
        g_Ppre[(dir*12800) + (v<<9) + p] = acc;
        return;
    }
    idx -= S2;
    if (idx < S4){
        int pr = idx >> 16; int rem = idx & 65535; int p = rem >> 7; int k = rem & 127;
        int j = ((p&3)<<7) + (p>>2);
        g_Wqperm[idx] = qWhh[(pr<<16) + (j<<7) + k];
        return;
    }
    idx -= S4;
    if (idx < S5){
        int pr = idx >> 14; int rem = idx & 16383; int b = rem >> 9; int p = rem & 511;
        int j = ((p&3)<<7) + (p>>2);
        float acc = qbih[(pr<<9)+j] + qbhh[(pr<<9)+j];
        const float* wr = qWih + (pr<<16) + (j<<7);
        const float* xr = qemb + (queries[b]<<7);
        for (int k=0;k<128;k++) acc += xr[k]*wr[k];
        g_Pq[(pr<<14) + (b<<9) + p] = acc;
        return;
    }
    idx -= S5;
    if (idx < S6){
        int dir = idx >> 17;
        int plane = (idx >> 16) & 1;
        int p = (idx >> 7) & 511;
        int k = idx & 127;
        int q = p & 15, b = p >> 4;
        int u = 4*b + ((q&7)>>1);
        int gate = (q<8) ? (q&1) : 2+(q&1);
        int j = (gate<<7) + u;
        float w = eWhh[(dir<<16) + (j<<7) + k];
        __nv_bfloat16 hi = __float2bfloat16(w);
        g_Bmma[idx] = plane ? __float2bfloat16(w - __bfloat162float(hi)) : hi;
    }
}

// fragment-major c offset for logical (m, u)
__device__ __forceinline__ int c_off(int m, int u){
    int mt=m>>7, ml=m&127, gnb=u>>5, ul=u&31;
    int warpM=ml>>5, mi=(ml>>4)&1, rh=(ml>>3)&1, rg=ml&7;
    int warpN=ul>>4, p2=(ul>>2)&3, tc=ul&3;
    int lane = rg*4+tc;
    return (mt*4+gnb)*4096 + (((warpM*2+mi)*2+warpN)*4+p2)*64 + rh*32 + lane;
}

// ---------------- entity LSTM step 0 ----------------
__global__ void ent_step0(int dir, int tIdx, const int* __restrict__ degs){
    int idx = blockIdx.x*blockDim.x + threadIdx.x;
    if (idx >= NENT*HID) return;
    int m = idx>>7, u = idx&127;
    int d = degs[(m<<3)+tIdx];
    float4 P = *(const float4*)(g_Ppre + (dir*12800) + (d<<9) + (u<<2));
    float cn = fsigm(P.x)*ftanh(P.z);
    float h  = fsigm(P.w)*ftanh(cn);
    g_c[c_off(m,u)] = cn;
    __nv_bfloat16 hh = __float2bfloat16(h);
    g_Amma[(size_t)0*NPAD*128 + (size_t)m*128 + u] = hh;
    g_Amma[(size_t)1*NPAD*128 + (size_t)m*128 + u] = __float2bfloat16(h - __bfloat162float(hh));
}

// ---------------- entity LSTM steps 1..7: mma.sync bf16x3 GEMM + fused cell ----------------
__global__ __launch_bounds__(256) void ent_mma(int inSel, int outSel, int dir, int tIdx,
                                               int finalF, const int* __restrict__ degs){
    extern __shared__ __align__(16) char sm[];
    char* Asm = sm;                 // 64KB: [plane][row 128][16 chunks of 16B, xor-swizzled]
    char* Bsm = sm + 65536;         // 64KB: same for B; reused as h stage after MMA
    int tid = threadIdx.x, lane = tid&31, wid = tid>>5;
    int warpM = wid&3, warpN = wid>>2;
    int gnb = blockIdx.x, mt = blockIdx.y;

    // ---- load A (hi+lo) and B (hi+lo) tiles with swizzle-on-store ----
    const __nv_bfloat16* Ag = g_Amma + (size_t)inSel*2*NPAD*128;
    #pragma unroll
    for (int j=0;j<16;j++){
        int i = tid + (j<<8);
        int plane = i>>11, row = (i>>4)&127, c = i&15;
        const uint4* s = (const uint4*)(Ag + ((size_t)plane*NPAD + (size_t)mt*128 + row)*128) + c;
        *(uint4*)(Asm + plane*32768 + row*256 + (((c ^ (row&7)))<<4)) = *s;
    }
    #pragma unroll
    for (int j=0;j<16;j++){
        int i = tid + (j<<8);
        int plane = i>>11, n = (i>>4)&127, c = i&15;
        const uint4* s = (const uint4*)(g_Bmma + (((size_t)(dir*2+plane)*512) + gnb*128 + n)*128) + c;
        *(uint4*)(Bsm + plane*32768 + n*256 + (((c ^ (n&7)))<<4)) = *s;
    }
    __syncthreads();

    uint32_t aBase = smem_u32(Asm), bBase = smem_u32(Bsm);
    int aRow = warpM*32 + (lane&7) + ((lane>>3)&1)*8;     // + mi*16
    int aHi  = lane>>4;
    int bRow = warpN*64 + (lane&7) + (lane>>4)*8;         // + nt2*16
    int bHi  = (lane>>3)&1;

    float acc[2][8][4];
    #pragma unroll
    for (int a1=0;a1<2;a1++)
        #pragma unroll
        for (int a2=0;a2<8;a2++)
            #pragma unroll
            for (int a3=0;a3<4;a3++) acc[a1][a2][a3]=0.f;

    const int paOff[3] = {0,0,32768};
    const int pbOff[3] = {0,32768,0};
    #pragma unroll
    for (int t3=0;t3<3;t3++){
        uint32_t aP = aBase + paOff[t3];
        uint32_t bP = bBase + pbOff[t3];
        #pragma unroll
        for (int kc=0;kc<8;kc++){
            uint32_t afr[2][4];
            #pragma unroll
            for (int mi=0;mi<2;mi++){
                int r = aRow + mi*16;
                LDSM4(afr[mi], aP + r*256 + (((2*kc + aHi) ^ (r&7))<<4));
            }
            uint32_t bfr[4][4];
            #pragma unroll
            for (int nt2=0;nt2<4;nt2++){
                int r = bRow + nt2*16;
                LDSM4(bfr[nt2], bP + r*256 + (((2*kc + bHi) ^ (r&7))<<4));
            }
            #pragma unroll
            for (int mi=0;mi<2;mi++)
                #pragma unroll
                for (int nt2=0;nt2<4;nt2++){
                    MMA16816(acc[mi][2*nt2],   afr[mi], bfr[nt2][0], bfr[nt2][1]);
                    MMA16816(acc[mi][2*nt2+1], afr[mi], bfr[nt2][2], bfr[nt2][3]);
                }
        }
    }
    __syncthreads();   // all MMA smem reads done; Bsm becomes the h stage

    // ---- fused LSTM cell epilogue on register fragments ----
    __nv_bfloat16* stH = (__nv_bfloat16*)Bsm;            // [128 rows][stride 40 bf16]
    __nv_bfloat16* stL = (__nv_bfloat16*)(Bsm + 10240);
    int tg = lane>>2, tc = lane&3;
    float* gH = dir ? g_hB : g_hF;
    #pragma unroll
    for (int mi=0;mi<2;mi++){
        #pragma unroll
        for (int rh=0;rh<2;rh++){
            int rloc = warpM*32 + mi*16 + rh*8 + tg;
            int m = mt*128 + rloc;
            bool mv = (m < NENT);
            int d = mv ? degs[(m<<3)+tIdx] : 0;
            const float4* Pb = (const float4*)(g_Ppre + dir*12800 + (d<<9));
            #pragma unroll
            for (int p2=0;p2<4;p2++){
                int ul = warpN*16 + p2*4 + tc;
                int u  = gnb*32 + ul;
                float4 P = Pb[u];
                float ig = fsigm(acc[mi][2*p2  ][rh*2+0] + P.x);
                float fg = fsigm(acc[mi][2*p2  ][rh*2+1] + P.y);
                float gg = ftanh(acc[mi][2*p2+1][rh*2+0] + P.z);
                float og = fsigm(acc[mi][2*p2+1][rh*2+1] + P.w);
                int cOff = (mt*4+gnb)*4096 + (((warpM*2+mi)*2+warpN)*4+p2)*64 + rh*32 + lane;
                float cp = mv ? g_c[cOff] : 0.f;
                float cn = fg*cp + ig*gg;
                if (mv) g_c[cOff] = cn;
                float h = og*ftanh(cn);
                if (finalF){
                    if (mv) gH[m*128+u] = h;
                } else {
                    __nv_bfloat16 hh = __float2bfloat16(h);
                    stH[rloc*40+ul] = hh;
                    stL[rloc*40+ul] = __float2bfloat16(h - __bfloat162float(hh));
                }
            }
        }
    }
    if (!finalF){
        __syncthreads();
        __nv_bfloat16* Ao = g_Amma + (size_t)outSel*2*NPAD*128;
        #pragma unroll
        for (int q=tid;q<1024;q+=256){
            int plane=q>>9, r2=q&511; int row=r2>>2, seg=r2&3;
            uint4 v = *(uint4*)((plane? stL:stH) + row*40 + seg*8);
            *(uint4*)(Ao + ((size_t)plane*NPAD + (size_t)mt*128 + row)*128 + gnb*32 + seg*8) = v;
        }
    }
}

// ---------------- entity attention ----------------
__global__ void ent_attn_kernel(const float* __restrict__ W, const float* __restrict__ bias){
    __shared__ float Ws[8192];
    int tid = threadIdx.x;
    for (int i=tid;i<8192;i+=256) Ws[i]=0.f;
    __syncthreads();
    for (int i=tid;i<24*256;i+=256){ int o=i>>8, k=i&255; Ws[(k<<5)+o]=W[i]; }
    __syncthreads();
    int lane = tid&31;
    int wid = (blockIdx.x<<3) + (tid>>5);
    int nw  = gridDim.x<<3;
    float bv = (lane<24)? bias[lane] : -1e30f;
    for (int n=wid; n<NENT; n+=nw){
        float acc = bv;
        const float* hf = g_hF + (n<<7);
        const float* hb = g_hB + (n<<7);
        for (int k=0;k<128;k++) acc += hf[k]*Ws[(k<<5)+lane];
        for (int k=0;k<128;k++) acc += hb[k]*Ws[((k+128)<<5)+lane];
        float mx = acc;
        for (int o=16;o;o>>=1) mx = fmaxf(mx, __shfl_xor_sync(0xffffffffu, mx, o));
        float e = (lane<24)? expf(acc-mx) : 0.f;
        float s = e;
        for (int o=16;o;o>>=1) s += __shfl_xor_sync(0xffffffffu, s, o);
        if (lane<24) g_eattn[n*24+lane] = e/s;
    }
}

__global__ void w_gather(const int* __restrict__ th, const int* __restrict__ rl){
    int e = blockIdx.x*blockDim.x + threadIdx.x;
    if (e < NEDGE) g_w[e] = g_eattn[th[e]*24 + rl[e]];
}

// ---------------- query LSTMs ----------------
__global__ void q_step0(){
    int idx = blockIdx.x*blockDim.x + threadIdx.x;
    if (idx >= 6*BQ*HID) return;
    int pr = idx/4096; int rem = idx&4095; int b = rem>>7; int u = rem&127;
    float4 P = *(const float4*)(g_Pq + (pr<<14) + (b<<9) + (u<<2));
    float cn = fsigm(P.x)*ftanh(P.z);
    g_qc[idx] = cn;
    g_qh[pr*3*4096 + rem] = fsigm(P.w)*ftanh(cn);
}

__global__ __launch_bounds__(256) void q_step(int s){
    int pr = blockIdx.y;
    int cb = blockIdx.x<<6;
    const float* h_in = g_qh + (pr*3 + s-1)*4096;
    float* h_out      = g_qh + (pr*3 + s)*4096;
    __shared__ float As[16][36];
    __shared__ float Bs[16][68];
    int tid=threadIdx.x;
    int ty=tid>>4, tx=tid&15;
    const float* Wp = g_Wqperm + (pr<<16);
    float acc[2][4] = {};
    int lrA = tid>>3; int kqA = (tid&7)<<1;
    int lrB = tid>>2; int kqB = (tid&3)<<2;
    for (int kb=0;kb<128;kb+=16){
        float2 a2 = *(const float2*)(h_in + (lrA<<7) + kb + kqA);
        float4 b4 = *(const float4*)(Wp + ((cb+lrB)<<7) + kb + kqB);
        As[kqA+0][lrA]=a2.x; As[kqA+1][lrA]=a2.y;
        Bs[kqB+0][lrB]=b4.x; Bs[kqB+1][lrB]=b4.y; Bs[kqB+2][lrB]=b4.z; Bs[kqB+3][lrB]=b4.w;
        __syncthreads();
        #pragma unroll
        for (int k=0;k<16;k++){
            float a0=As[k][(ty<<1)], a1=As[k][(ty<<1)+1];
            float4 b=*(const float4*)&Bs[k][tx<<2];
            acc[0][0]+=a0*b.x; acc[0][1]+=a0*b.y; acc[0][2]+=a0*b.z; acc[0][3]+=a0*b.w;
            acc[1][0]+=a1*b.x; acc[1][1]+=a1*b.y; acc[1][2]+=a1*b.z; acc[1][3]+=a1*b.w;
        }
        __syncthreads();
    }
    int u = (cb>>2)+tx;
    #pragma unroll
    for (int i=0;i<2;i++){
        int b = (ty<<1)+i;
        float4 P = *(const float4*)(g_Pq + (pr<<14) + (b<<9) + cb + (tx<<2));
        float ig=fsigm(acc[i][0]+P.x), fg=fsigm(acc[i][1]+P.y);
        float gg=ftanh(acc[i][2]+P.z), og=fsigm(acc[i][3]+P.w);
        int ci = pr*4096 + (b<<7) + u;
        float cn = fg*g_qc[ci] + ig*gg;
        g_qc[ci]=cn;
        h_out[(b<<7)+u]=og*ftanh(cn);
    }
}

__global__ void q_attn_kernel(const float* __restrict__ W, const float* __restrict__ bias){
    __shared__ float Ws[8192];
    int tid=threadIdx.x;
    for (int i=tid;i<8192;i+=256) Ws[i]=0.f;
    __syncthreads();
    for (int i=tid;i<25*256;i+=256){ int o=i>>8,k=i&255; Ws[(k<<5)+o]=W[i]; }
    __syncthreads();
    int lane=tid&31;
    int gw=(blockIdx.x<<3)+(tid>>5);
    if (gw>=288) return;
    int b=gw&31, rt=gw>>5; int r=rt/3, t=rt%3;
    const float* hf = g_qh + ((r*2  )*3 + t    )*4096 + (b<<7);
    const float* hb = g_qh + ((r*2+1)*3 + (2-t))*4096 + (b<<7);
    float acc = (lane<25)? bias[lane] : -1e30f;
    for (int k=0;k<128;k++) acc += hf[k]*Ws[(k<<5)+lane];
    for (int k=0;k<128;k++) acc += hb[k]*Ws[((k+128)<<5)+lane];
    float mx=acc;
    for (int o=16;o;o>>=1) mx=fmaxf(mx,__shfl_xor_sync(0xffffffffu,mx,o));
    float e=(lane<25)?expf(acc-mx):0.f;
    float s=e;
    for (int o=16;o;o>>=1) s+=__shfl_xor_sync(0xffffffffu,s,o);
    if (lane<25) g_qattn[rt*800 + b*25 + lane] = e/s;
}

// ---------------- propagation ----------------
__global__ void mem_init(const int* __restrict__ heads){
    int idx=blockIdx.x*blockDim.x+threadIdx.x;
    if (idx>=NENT*BQ) return;
    int n=idx>>5, b=idx&31;
    g_mem[idx] = (heads[b]==n)? 1.f : 0.f;
}

__global__ void prop_init(int rt){
    int idx=blockIdx.x*blockDim.x+threadIdx.x;
    if (idx<BQ) g_sums[idx]=0.f;
    if (idx<NENT*BQ)
        g_added[idx] = g_mem[idx]*g_qattn[rt*800 + (idx&31)*25 + 24];
}

__global__ void edge_kernel(int rt, const int* __restrict__ rl,
                            const int* __restrict__ th, const int* __restrict__ tt){
    __shared__ float qs[800];
    const float* qa = g_qattn + rt*800;
    for (int i=threadIdx.x;i<800;i+=blockDim.x) qs[i]=qa[i];
    __syncthreads();
    int lane = threadIdx.x&31;
    int wid = (blockIdx.x*blockDim.x+threadIdx.x)>>5;
    int nw  = (gridDim.x*blockDim.x)>>5;
    for (int e=wid; e<NEDGE; e+=nw){
        int re=rl[e], he=th[e], te=tt[e];
        float we=g_w[e];
        float mh = g_mem[(he<<5)+lane];
        float mt = g_mem[(te<<5)+lane];
        float qf = qs[lane*25+re]*we;
        float qr = qs[lane*25+re+12]*we;
        atomicAdd(&g_added[(te<<5)+lane], qf*mh);
        atomicAdd(&g_added[(he<<5)+lane], qr*mt);
    }
}

__global__ void colsum_kernel(){
    int lane=threadIdx.x&31, w=threadIdx.x>>5;
    float acc=0.f;
    for (int row=(blockIdx.x<<3)+w; row<NENT; row+=gridDim.x<<3)
        acc += g_added[(row<<5)+lane];
    __shared__ float sh[8][32];
    sh[w][lane]=acc;
    __syncthreads();
    if (w==0){
        float s=0.f;
        #pragma unroll
        for (int i=0;i<8;i++) s+=sh[i][lane];
        atomicAdd(&g_sums[lane], s);
    }
}

__global__ void norm_kernel(){
    int idx=blockIdx.x*blockDim.x+threadIdx.x;
    if (idx>=NENT*BQ) return;
    g_mem[idx] = g_added[idx] / fmaxf(1e-20f, g_sums[idx&31]);
}

__global__ void trans_add(float* __restrict__ out, int accum){
    __shared__ float tile[32][33];
    int n0=blockIdx.x<<5;
    int tx=threadIdx.x, ty=threadIdx.y;
    int n=n0+ty;
    tile[ty][tx] = (n<NENT)? g_mem[(n<<5)+tx] : 0.f;
    __syncthreads();
    int nn=n0+tx;
    if (nn<NENT){
        float v=tile[tx][ty];
        if (accum) out[ty*NENT+nn] += v; else out[ty*NENT+nn] = v;
    }
}

// ---------------- host ----------------
extern "C" void kernel_launch(void* const* d_in, const int* in_sizes, int n_in,
                              void* d_out, int out_size){
    const int*   queries=(const int*)d_in[0];
    const int*   heads  =(const int*)d_in[1];
    const int*   rels   =(const int*)d_in[2];
    const int*   t_heads=(const int*)d_in[3];
    const int*   t_tails=(const int*)d_in[4];
    const int*   degs   =(const int*)d_in[5];
    const float* qemb=(const float*)d_in[6];
    const float* eemb=(const float*)d_in[7];
    const float* qWih=(const float*)d_in[8];
    const float* qWhh=(const float*)d_in[9];
    const float* qbih=(const float*)d_in[10];
    const float* qbhh=(const float*)d_in[11];
    const float* eWih=(const float*)d_in[12];
    const float* eWhh=(const float*)d_in[13];
    const float* ebih=(const float*)d_in[14];
    const float* ebhh=(const float*)d_in[15];
    const float* qlW=(const float*)d_in[16];
    const float* qlb=(const float*)d_in[17];
    const float* elW=(const float*)d_in[18];
    const float* elb=(const float*)d_in[19];
    float* out=(float*)d_out;

    const int DSMEM = 131072;
    cudaFuncSetAttribute(ent_mma, cudaFuncAttributeMaxDynamicSharedMemorySize, DSMEM);

    prep_kernel<<<(PREP_TOT+255)/256,256>>>(eWih,eWhh,ebih,ebhh,eemb,
                                            qWih,qWhh,qbih,qbhh,qemb,queries);
    // entity BiLSTM on tensor cores (mma.sync)
    for (int dir=0; dir<2; dir++){
        ent_step0<<<25000,256>>>(dir, dir?7:0, degs);
        for (int s=1; s<8; s++){
            int t = dir? (7-s) : s;
            ent_mma<<<dim3(4,MTILES),256,DSMEM>>>((s-1)&1, s&1, dir, t, (s==7)?1:0, degs);
        }
    }
    ent_attn_kernel<<<1024,256>>>(elW, elb);
    w_gather<<<(NEDGE+255)/256,256>>>(t_heads, rels);

    // query BiLSTMs
    q_step0<<<96,256>>>();
    q_step<<<dim3(8,6),256>>>(1);
    q_step<<<dim3(8,6),256>>>(2);
    q_attn_kernel<<<36,256>>>(qlW, qlb);

    // propagation
    for (int r=0; r<3; r++){
        mem_init<<<6250,256>>>(heads);
        for (int t=0; t<3; t++){
            int rt = r*3+t;
            prop_init<<<6250,256>>>(rt);
            edge_kernel<<<1024,256>>>(rt, rels, t_heads, t_tails);
            colsum_kernel<<<512,256>>>();
            norm_kernel<<<6250,256>>>();
        }
        trans_add<<<1563,dim3(32,32)>>>(out, r);
    }
}